// round 9
// baseline (speedup 1.0000x reference)
#include <cuda_runtime.h>
#include <cuda_bf16.h>
#include <cstddef>

#define NB   16
#define ND   4
#define NF   481
#define NT   500
#define CH   16
#define NH   32
#define NSEQ (NB * NF)              // 7696
#define PROB_ELEMS (NSEQ * NT)      // 3,848,000
#define H_ELEMS    (NSEQ * NH)      // 246,272

#define NGRP (NSEQ / 8)             // 962 groups of 8 sequences

typedef unsigned long long u64;

// conv output x, layout [gw8][t][g8][c]
__device__ float g_x2[(size_t)NGRP * NT * 8 * CH];
// fallback sink for h_last
__device__ float g_hdump[H_ELEMS];

// ---------------------------------------------------------------------------
// packed f32x2 helpers
// ---------------------------------------------------------------------------
__device__ __forceinline__ u64 fma2(u64 a, u64 b, u64 c) {
    u64 d;
    asm("fma.rn.f32x2 %0, %1, %2, %3;" : "=l"(d) : "l"(a), "l"(b), "l"(c));
    return d;
}
__device__ __forceinline__ u64 pack2(float lo, float hi) {
    u64 d;
    asm("mov.b64 %0, {%1, %2};" : "=l"(d) : "f"(lo), "f"(hi));
    return d;
}
__device__ __forceinline__ void unpack2(u64 v, float& lo, float& hi) {
    asm("mov.b64 {%0, %1}, %2;" : "=f"(lo), "=f"(hi) : "l"(v));
}
__device__ __forceinline__ float sigm(float v) {
    return __fdividef(1.f, 1.f + __expf(-v));
}
__device__ __forceinline__ float tanh_f(float v) {
    return __fdividef(2.f, 1.f + __expf(-2.f * v)) - 1.f;
}

// ---------------------------------------------------------------------------
// Kernel 1: fused conv1(K=9,pad=4)+PReLU -> conv2(K=5,pad=2)+PReLU  (f32x2)
// (unchanged from R6)
// ---------------------------------------------------------------------------
#define FT 32
#define TT 32
#define FIN 44
#define FC1 36

#define W1D 576
#define W2D 1280
#define BD  32

__global__ __launch_bounds__(256, 2) void conv_kernel(
    const float* __restrict__ feat,
    const float* __restrict__ w1, const float* __restrict__ b1,
    const float* __restrict__ a1p,
    const float* __restrict__ w2, const float* __restrict__ b2,
    const float* __restrict__ a2p)
{
    extern __shared__ u64 smu[];
    u64* s_w1d = smu;
    u64* s_w2d = smu + W1D;
    u64* s_bd  = s_w2d + W2D;
    float* s_in = (float*)(s_bd + BD);
    float* s_c1 = s_in + ND * FIN * TT;

    const int tid = threadIdx.x;
    const int t0 = blockIdx.x * TT;
    const int f0 = blockIdx.y * FT;
    const int b  = blockIdx.z;
    const float a1 = a1p[0];
    const float a2 = a2p[0];

    for (int i = tid; i < W1D;  i += 256) { float w = w1[i]; s_w1d[i] = pack2(w, w); }
    for (int i = tid; i < W2D; i += 256)  { float w = w2[i]; s_w2d[i] = pack2(w, w); }
    if (tid < 16)       { float v = b1[tid];      s_bd[tid] = pack2(v, v); }
    else if (tid < 32)  { float v = b2[tid - 16]; s_bd[tid] = pack2(v, v); }

    for (int i = tid; i < ND * FIN * TT; i += 256) {
        int t  = i & (TT - 1);
        int fl = (i / TT) % FIN;
        int d  = i / (TT * FIN);
        int f  = f0 - 6 + fl;
        int tg = t0 + t;
        float v = 0.f;
        if (f >= 0 && f < NF && tg < NT)
            v = feat[((b * ND + d) * NF + f) * NT + tg];
        s_in[i] = v;
    }
    __syncthreads();

    for (int u = tid; u < FC1 * 8; u += 256) {
        int tq  = u & 7;
        int f1i = u >> 3;
        int f1  = f0 - 2 + f1i;
        u64 a2r[CH][2];
        if (f1 >= 0 && f1 < NF) {
            #pragma unroll
            for (int c = 0; c < CH; c++) { a2r[c][0] = s_bd[c]; a2r[c][1] = s_bd[c]; }
            #pragma unroll
            for (int d = 0; d < ND; d++)
                #pragma unroll
                for (int k = 0; k < 9; k++) {
                    const u64* vp = (const u64*)&s_in[(d * FIN + f1i + k) * TT + tq * 4];
                    u64 v0 = vp[0], v1 = vp[1];
                    #pragma unroll
                    for (int c = 0; c < CH; c++) {
                        u64 w = s_w1d[(c * ND + d) * 9 + k];
                        a2r[c][0] = fma2(w, v0, a2r[c][0]);
                        a2r[c][1] = fma2(w, v1, a2r[c][1]);
                    }
                }
            #pragma unroll
            for (int c = 0; c < CH; c++)
                #pragma unroll
                for (int hh = 0; hh < 2; hh++) {
                    float x0, x1;
                    unpack2(a2r[c][hh], x0, x1);
                    x0 = x0 >= 0.f ? x0 : a1 * x0;
                    x1 = x1 >= 0.f ? x1 : a1 * x1;
                    a2r[c][hh] = pack2(x0, x1);
                }
        } else {
            #pragma unroll
            for (int c = 0; c < CH; c++) { a2r[c][0] = 0ull; a2r[c][1] = 0ull; }
        }
        #pragma unroll
        for (int c = 0; c < CH; c++) {
            u64* op = (u64*)&s_c1[(c * FC1 + f1i) * TT + tq * 4];
            op[0] = a2r[c][0]; op[1] = a2r[c][1];
        }
    }
    __syncthreads();

    {
        int tq  = tid & 7;
        int f2i = tid >> 3;
        u64 a2r[CH][2];
        #pragma unroll
        for (int c = 0; c < CH; c++) { a2r[c][0] = s_bd[16 + c]; a2r[c][1] = s_bd[16 + c]; }
        #pragma unroll
        for (int ci = 0; ci < CH; ci++)
            #pragma unroll
            for (int k = 0; k < 5; k++) {
                const u64* vp = (const u64*)&s_c1[(ci * FC1 + f2i + k) * TT + tq * 4];
                u64 v0 = vp[0], v1 = vp[1];
                #pragma unroll
                for (int co = 0; co < CH; co++) {
                    u64 w = s_w2d[(co * CH + ci) * 5 + k];
                    a2r[co][0] = fma2(w, v0, a2r[co][0]);
                    a2r[co][1] = fma2(w, v1, a2r[co][1]);
                }
            }
        float ov[CH][4];
        #pragma unroll
        for (int c = 0; c < CH; c++) {
            unpack2(a2r[c][0], ov[c][0], ov[c][1]);
            unpack2(a2r[c][1], ov[c][2], ov[c][3]);
            #pragma unroll
            for (int tw = 0; tw < 4; tw++) {
                float x = ov[c][tw];
                ov[c][tw] = x >= 0.f ? x : a2 * x;
            }
        }
        int f = f0 + f2i;
        if (f < NF) {
            int seq = b * NF + f;
            size_t base = (size_t)(seq >> 3) * NT * 128 + (seq & 7) * 16;
            #pragma unroll
            for (int tw = 0; tw < 4; tw++) {
                int t = t0 + tq * 4 + tw;
                if (t < NT) {
                    float* o = g_x2 + base + (size_t)t * 128;
                    #pragma unroll
                    for (int c4 = 0; c4 < 4; c4++)
                        *(float4*)(o + c4 * 4) = make_float4(
                            ov[c4 * 4 + 0][tw], ov[c4 * 4 + 1][tw],
                            ov[c4 * 4 + 2][tw], ov[c4 * 4 + 3][tw]);
                }
            }
        }
    }
}

// ---------------------------------------------------------------------------
// Kernel 2: GRU, GPW=4. 962 blocks x 64 threads = 2 INDEPENDENT warps that
// share the 16KB w_hh r/z table (one startup __syncthreads, none per step).
// Warp wp handles 4 seqs: sbase = blockIdx.x*8 + wp*4. Lane j = hidden unit.
// hh-part: f32x2 packed over seq pairs (whhA dup float4 smem; whn packed regs
// + MOV-dup). x-part: scalar FFMA (w_ih plain-float regs, no duplication).
// fc via 4-value register butterfly.
// ---------------------------------------------------------------------------
__global__ __launch_bounds__(64, 7) void gru_kernel(
    const float* __restrict__ h0,
    const float* __restrict__ w_ih, const float* __restrict__ w_hh,
    const float* __restrict__ b_ih, const float* __restrict__ b_hh,
    const float* __restrict__ fc_w, const float* __restrict__ fc_b,
    float* __restrict__ prob, float* __restrict__ hlast)
{
    __shared__ float4 s_whhA[NH][NH];     // [k][j] = (wr,wr,wz,wz)  16KB shared
    __shared__ u64   s_hh[2][NH][2];      // per-warp h pairs         1KB
    __shared__ float s_xT[2][CH][4];      // per-warp x [c][g]        512B

    const int tid  = threadIdx.x;
    const int lane = tid & 31;
    const int wp   = tid >> 5;
    const int j    = lane;

    for (int i = tid; i < NH * NH; i += 64) {
        int k = i >> 5, jj = i & 31;
        float wr = w_hh[jj * NH + k];
        float wz = w_hh[(NH + jj) * NH + k];
        s_whhA[k][jj] = make_float4(wr, wr, wz, wz);
    }

    const int gw8 = blockIdx.x;
    const int sbase = gw8 * 8 + wp * 4;

    // whn packed non-dup: (wn[2k2], wn[2k2+1])
    u64 whnp[NH / 2];
    #pragma unroll
    for (int k2 = 0; k2 < NH / 2; k2++)
        whnp[k2] = pack2(w_hh[(2 * NH + j) * NH + 2 * k2],
                         w_hh[(2 * NH + j) * NH + 2 * k2 + 1]);

    // w_ih scalar registers
    float wxr[CH], wxz[CH], wxn[CH];
    #pragma unroll
    for (int c = 0; c < CH; c++) {
        wxr[c] = w_ih[j * CH + c];
        wxz[c] = w_ih[(NH + j) * CH + c];
        wxn[c] = w_ih[(2 * NH + j) * CH + c];
    }

    const float brf  = b_ih[j] + b_hh[j];
    const float bzf  = b_ih[NH + j] + b_hh[NH + j];
    const float bxnf = b_ih[2 * NH + j];
    const float bhnf = b_hh[2 * NH + j];
    const u64 br2  = pack2(brf, brf);
    const u64 bz2  = pack2(bzf, bzf);
    const u64 bhn2 = pack2(bhnf, bhnf);
    const float fcwj = fc_w[j];
    const float fcb  = fc_b[0];

    float hreg[4];
    #pragma unroll
    for (int q = 0; q < 4; q++) hreg[q] = h0[(sbase + q) * NH + j];
    {
        ulonglong2 v;
        v.x = pack2(hreg[0], hreg[1]); v.y = pack2(hreg[2], hreg[3]);
        *(ulonglong2*)&s_hh[wp][j][0] = v;
    }

    // x: lane -> (g = lane>>3, c2 = lane&7); layout [gw8][t][g8][c]
    const int lg = lane >> 3, lc2 = lane & 7;
    const float* xptr = g_x2 + (size_t)gw8 * NT * 128 + (wp * 4 + lg) * 16 + 2 * lc2;
    float2 xv = *(const float2*)xptr;

    __syncthreads();   // whhA staged; initial h stores visible

    for (int t = 0; t < NT; t++) {
        s_xT[wp][2 * lc2 + 0][lg] = xv.x;
        s_xT[wp][2 * lc2 + 1][lg] = xv.y;
        __syncwarp();
        if (t + 1 < NT)
            xv = *(const float2*)(xptr + (size_t)(t + 1) * 128);

        // packed hh accumulators: pair0 = seqs(0,1), pair1 = seqs(2,3)
        u64 ar0 = br2, ar1 = br2, az0 = bz2, az1 = bz2, an0 = bhn2, an1 = bhn2;

        #pragma unroll
        for (int k2 = 0; k2 < NH / 2; k2++) {
            float wn0, wn1;
            unpack2(whnp[k2], wn0, wn1);
            {
                int k = 2 * k2;
                ulonglong2 wA = *(const ulonglong2*)&s_whhA[k][j];
                ulonglong2 hv = *(const ulonglong2*)&s_hh[wp][k][0];
                u64 wnn = pack2(wn0, wn0);
                ar0 = fma2(wA.x, hv.x, ar0);  ar1 = fma2(wA.x, hv.y, ar1);
                az0 = fma2(wA.y, hv.x, az0);  az1 = fma2(wA.y, hv.y, az1);
                an0 = fma2(wnn,  hv.x, an0);  an1 = fma2(wnn,  hv.y, an1);
            }
            {
                int k = 2 * k2 + 1;
                ulonglong2 wA = *(const ulonglong2*)&s_whhA[k][j];
                ulonglong2 hv = *(const ulonglong2*)&s_hh[wp][k][0];
                u64 wnn = pack2(wn1, wn1);
                ar0 = fma2(wA.x, hv.x, ar0);  ar1 = fma2(wA.x, hv.y, ar1);
                az0 = fma2(wA.y, hv.x, az0);  az1 = fma2(wA.y, hv.y, az1);
                an0 = fma2(wnn,  hv.x, an0);  an1 = fma2(wnn,  hv.y, an1);
            }
        }

        // x-part: scalar FFMA per seq
        float axr[4] = {0.f, 0.f, 0.f, 0.f};
        float axz[4] = {0.f, 0.f, 0.f, 0.f};
        float axn[4] = {bxnf, bxnf, bxnf, bxnf};
        #pragma unroll
        for (int c = 0; c < CH; c++) {
            float4 xq = *(const float4*)&s_xT[wp][c][0];
            axr[0] = fmaf(wxr[c], xq.x, axr[0]); axr[1] = fmaf(wxr[c], xq.y, axr[1]);
            axr[2] = fmaf(wxr[c], xq.z, axr[2]); axr[3] = fmaf(wxr[c], xq.w, axr[3]);
            axz[0] = fmaf(wxz[c], xq.x, axz[0]); axz[1] = fmaf(wxz[c], xq.y, axz[1]);
            axz[2] = fmaf(wxz[c], xq.z, axz[2]); axz[3] = fmaf(wxz[c], xq.w, axz[3]);
            axn[0] = fmaf(wxn[c], xq.x, axn[0]); axn[1] = fmaf(wxn[c], xq.y, axn[1]);
            axn[2] = fmaf(wxn[c], xq.z, axn[2]); axn[3] = fmaf(wxn[c], xq.w, axn[3]);
        }

        // gates
        float arv[4], azv[4], anv[4];
        unpack2(ar0, arv[0], arv[1]); unpack2(ar1, arv[2], arv[3]);
        unpack2(az0, azv[0], azv[1]); unpack2(az1, azv[2], azv[3]);
        unpack2(an0, anv[0], anv[1]); unpack2(an1, anv[2], anv[3]);

        float hnew[4];
        #pragma unroll
        for (int q = 0; q < 4; q++) {
            float r = sigm(arv[q] + axr[q]);
            float z = sigm(azv[q] + axz[q]);
            float n = tanh_f(fmaf(r, anv[q], axn[q]));
            hnew[q] = fmaf(z, hreg[q] - n, n);
        }

        __syncwarp();   // all hh reads for this step complete before overwrite
        {
            ulonglong2 v;
            v.x = pack2(hnew[0], hnew[1]); v.y = pack2(hnew[2], hnew[3]);
            *(ulonglong2*)&s_hh[wp][j][0] = v;
        }

        // fc + sigmoid via 4-value register butterfly
        float pc0 = hnew[0] * fcwj, pc1 = hnew[1] * fcwj;
        float pc2 = hnew[2] * fcwj, pc3 = hnew[3] * fcwj;
        #pragma unroll
        for (int off = 16; off; off >>= 1) {
            pc0 += __shfl_xor_sync(0xffffffffu, pc0, off);
            pc1 += __shfl_xor_sync(0xffffffffu, pc1, off);
            pc2 += __shfl_xor_sync(0xffffffffu, pc2, off);
            pc3 += __shfl_xor_sync(0xffffffffu, pc3, off);
        }
        if (lane == 0) prob[(size_t)(sbase + 0) * NT + t] = sigm(pc0 + fcb);
        if (lane == 1) prob[(size_t)(sbase + 1) * NT + t] = sigm(pc1 + fcb);
        if (lane == 2) prob[(size_t)(sbase + 2) * NT + t] = sigm(pc2 + fcb);
        if (lane == 3) prob[(size_t)(sbase + 3) * NT + t] = sigm(pc3 + fcb);

        #pragma unroll
        for (int q = 0; q < 4; q++) hreg[q] = hnew[q];
    }

    #pragma unroll
    for (int q = 0; q < 4; q++)
        hlast[(sbase + q) * NH + j] = hreg[q];
}

// ---------------------------------------------------------------------------
extern "C" void kernel_launch(void* const* d_in, const int* in_sizes, int n_in,
                              void* d_out, int out_size)
{
    const float* feat  = (const float*)d_in[0];
    const float* h0    = (const float*)d_in[1];
    const float* w1    = (const float*)d_in[2];
    const float* b1    = (const float*)d_in[3];
    const float* a1    = (const float*)d_in[4];
    const float* w2    = (const float*)d_in[5];
    const float* b2    = (const float*)d_in[6];
    const float* a2    = (const float*)d_in[7];
    const float* w_ih  = (const float*)d_in[8];
    const float* w_hh  = (const float*)d_in[9];
    const float* b_ih  = (const float*)d_in[10];
    const float* b_hh  = (const float*)d_in[11];
    const float* fc_w  = (const float*)d_in[12];
    const float* fc_b  = (const float*)d_in[13];

    float* prob = (float*)d_out;
    float* hlast;
    if (out_size >= PROB_ELEMS + H_ELEMS) {
        hlast = prob + PROB_ELEMS;
    } else {
        void* p = nullptr;
        cudaGetSymbolAddress(&p, g_hdump);
        hlast = (float*)p;
    }

    const int smem_bytes = (W1D + W2D + BD) * 8 + (ND * FIN * TT + CH * FC1 * TT) * 4;
    cudaFuncSetAttribute(conv_kernel, cudaFuncAttributeMaxDynamicSharedMemorySize,
                         smem_bytes);

    dim3 cgrid((NT + TT - 1) / TT, (NF + FT - 1) / FT, NB);
    conv_kernel<<<cgrid, 256, smem_bytes>>>(feat, w1, b1, a1, w2, b2, a2);

    gru_kernel<<<NGRP, 64>>>(h0, w_ih, w_hh, b_ih, b_hh, fc_w, fc_b,
                             prob, hlast);
}